// round 7
// baseline (speedup 1.0000x reference)
#include <cuda_runtime.h>
#include <cuda_bf16.h>
#include <cub/block/block_radix_sort.cuh>

// loss = (1/B) * sum_rows sum_{rank i<j} |t_i - t_j| * (dv_j - dv_i),  dv_k = log2(k+3)
// (sigmoid eliminated: sigma(x)+sigma(-x)=1; dv monotone in rank.)
// Factored: loss_row = sum_k dv_k * (2*L_k - F_k),
//   L_k = sum_{rank i<k} |t_i - t_k|,  F_k = sum_all |t_i - t_k|
// Rank-tiles of 128; per tile target-sorted + prefix sums give O(1) range-|diff| queries:
//   A(t) = t*(2c-TS) - 2*St(c) + Stot,  c = #{t_i <= t} via binary search.
// K1 (fused): CUB BlockRadixSort by pred desc (payload target) -> g_st; then per-128-tile
//             bitonic target sort (1 smem stage + shfl) + warp-scan prefix -> g_ts, g_pt.
// K2: per element: 16 interleaved binary searches + O(1) combines + in-tile brute, x dv.

constexpr int BB = 32;
constexpr int NN = 2048;
constexpr int TS = 128;
constexpr int NT = NN / TS;   // 16

__device__ float g_st[BB * NN];
__device__ float g_ts[BB * NN];
__device__ float g_pt[BB * NN];

__device__ __forceinline__ unsigned mono32(unsigned u) {
    return (u & 0x80000000u) ? ~u : (u | 0x80000000u);
}
__device__ __forceinline__ float unmono32(unsigned m) {
    unsigned o = (m & 0x80000000u) ? (m & 0x7fffffffu) : ~m;
    return __uint_as_float(o);
}
__device__ __forceinline__ unsigned cex32(unsigned v, unsigned o, int p, int j, int k) {
    bool up  = ((p & k) == 0);
    bool low = ((p & j) == 0);
    unsigned mn = (v < o) ? v : o;
    unsigned mx = (v < o) ? o : v;
    return (low == up) ? mn : mx;
}

// ---------- K1: radix sort by pred desc + fused tile prep ----------
using BRS = cub::BlockRadixSort<unsigned, 1024, 2, unsigned>;

union SortSmem {
    typename BRS::TempStorage cub;
    unsigned sbuf[NN];
};

__global__ void __launch_bounds__(1024) sort_kernel(const float* __restrict__ preds,
                                                    const float* __restrict__ targets,
                                                    float* __restrict__ out) {
    __shared__ SortSmem S;
    __shared__ float wsums[32];

    const int row = blockIdx.x;
    const int t   = threadIdx.x;
    if (row == 0 && t == 0) out[0] = 0.0f;   // stream-ordered before K2's atomics

    const float2 pv = ((const float2*)(preds + row * NN))[t];
    const float2 tv = ((const float2*)(targets + row * NN))[t];

    unsigned keys[2] = { mono32(__float_as_uint(pv.x)), mono32(__float_as_uint(pv.y)) };
    unsigned vals[2] = { __float_as_uint(tv.x), __float_as_uint(tv.y) };

    BRS(S.cub).SortDescending(keys, vals);   // stable; blocked: thread t -> ranks 2t, 2t+1
    __syncthreads();                          // temp storage dead; reuse as sbuf

    const float st0 = __uint_as_float(vals[0]);
    const float st1 = __uint_as_float(vals[1]);
    ((float2*)(g_st + row * NN))[t] = make_float2(st0, st1);

    // per-128-tile ascending bitonic sort of targets (keys only)
    // element indices within tile: i0 = 2l, i1 = 2l+1, l = t & 63
    const int l  = t & 63;
    const int i0 = 2 * l, i1 = i0 + 1;
    unsigned m0 = mono32(vals[0]);
    unsigned m1 = mono32(vals[1]);

#pragma unroll
    for (int k = 2; k <= TS; k <<= 1) {
#pragma unroll
        for (int j = k >> 1; j > 0; j >>= 1) {
            if (j == 1) {
                bool up = ((i0 & k) == 0);
                unsigned mn = (m0 < m1) ? m0 : m1;
                unsigned mx = (m0 < m1) ? m1 : m0;
                m0 = up ? mn : mx;
                m1 = up ? mx : mn;
            } else if (j == 64) {
                S.sbuf[2 * t]     = m0;
                S.sbuf[2 * t + 1] = m1;
                __syncthreads();
                unsigned o0 = S.sbuf[(2 * t) ^ 64];
                unsigned o1 = S.sbuf[(2 * t + 1) ^ 64];
                __syncthreads();
                m0 = cex32(m0, o0, i0, j, k);
                m1 = cex32(m1, o1, i1, j, k);
            } else {          // j in [2, 32] -> partner thread t ^ (j>>1), same warp
                int dt = j >> 1;
                unsigned o0 = __shfl_xor_sync(0xffffffffu, m0, dt);
                unsigned o1 = __shfl_xor_sync(0xffffffffu, m1, dt);
                m0 = cex32(m0, o0, i0, j, k);
                m1 = cex32(m1, o1, i1, j, k);
            }
        }
    }

    const float ts0 = unmono32(m0);
    const float ts1 = unmono32(m1);

    // inclusive prefix sums within each 128-tile (2 warps per tile)
    const int lane = t & 31;
    float pair = ts0 + ts1;
    float sc = pair;
#pragma unroll
    for (int off = 1; off < 32; off <<= 1) {
        float y = __shfl_up_sync(0xffffffffu, sc, off);
        if (lane >= off) sc += y;
    }
    if (lane == 31) wsums[t >> 5] = sc;
    __syncthreads();
    float base = ((t >> 5) & 1) ? wsums[(t >> 5) - 1] : 0.f;   // 2nd warp of tile
    float p0 = base + (sc - pair) + ts0;
    float p1 = p0 + ts1;

    ((float2*)(g_ts + row * NN))[t] = make_float2(ts0, ts1);
    ((float2*)(g_pt + row * NN))[t] = make_float2(p0, p1);
}

// ---------- K2: per-element queries ----------
__global__ void __launch_bounds__(256) query_kernel(float* __restrict__ out) {
    __shared__ float ts_s[NN];
    __shared__ float pt_s[NN];
    __shared__ float st_s[256];
    __shared__ float wsum[8];

    const int row = blockIdx.y;
    const int ch  = blockIdx.x;      // 0..7
    const int tid = threadIdx.x;

    for (int i = tid; i < NN; i += 256) {
        ts_s[i] = g_ts[row * NN + i];
        pt_s[i] = g_pt[row * NN + i];
    }
    st_s[tid] = g_st[row * NN + ch * 256 + tid];
    __syncthreads();

    const int a = ch * 256 + tid;
    const int T = a >> 7;
    const float ta = st_s[tid];
    const float da = __log2f((float)(a + 3));

    // 16 interleaved binary searches: c[u] = #{t_i <= ta} in tile u
    int c[NT];
#pragma unroll
    for (int u = 0; u < NT; u++) c[u] = 0;
#pragma unroll
    for (int s = TS / 2; s > 0; s >>= 1) {
#pragma unroll
        for (int u = 0; u < NT; u++) {
            if (ts_s[u * TS + c[u] + s - 1] <= ta) c[u] += s;
        }
    }

    float acc = 0.f;
#pragma unroll
    for (int u = 0; u < NT; u++) {
        int cc = c[u];
        float St   = cc ? pt_s[u * TS + cc - 1] : 0.f;
        float Stot = pt_s[u * TS + TS - 1];
        float A = ta * (float)(2 * cc - TS) - 2.f * St + Stot;
        acc += (u < T) ? A : -A;
    }

    // within-own-tile earlier-rank brute force: L_own
    const int base = tid & TS;
    const int l    = tid & (TS - 1);
    float L = 0.f;
    for (int i = 0; i < l; i++)
        L += fabsf(st_s[base + i] - ta);

    float res = da * (acc + 2.f * L);

#pragma unroll
    for (int off = 16; off > 0; off >>= 1)
        res += __shfl_down_sync(0xffffffffu, res, off);
    if ((tid & 31) == 0) wsum[tid >> 5] = res;
    __syncthreads();
    if (tid == 0) {
        float bs = 0.f;
#pragma unroll
        for (int w = 0; w < 8; w++) bs += wsum[w];
        atomicAdd(out, bs * (1.0f / (float)BB));
    }
}

extern "C" void kernel_launch(void* const* d_in, const int* in_sizes, int n_in,
                              void* d_out, int out_size) {
    const float* preds   = (const float*)d_in[0];
    const float* targets = (const float*)d_in[1];
    float* out = (float*)d_out;

    sort_kernel<<<BB, 1024>>>(preds, targets, out);

    dim3 g2(NN / 256, BB);
    query_kernel<<<g2, 256>>>(out);
}

// round 9
// speedup vs baseline: 1.0809x; 1.0809x over previous
#include <cuda_runtime.h>
#include <cuda_bf16.h>
#include <cub/block/block_radix_sort.cuh>

// loss = (1/B) * sum_rows sum_{rank i<j} |t_i - t_j| * (dv_j - dv_i),  dv_k = log2(k+3)
// (sigmoid eliminated: sigma(x)+sigma(-x)=1; dv monotone in rank.)
// Factored: loss_row = sum_k dv_k * (2*L_k - F_k),
//   L_k = sum_{rank i<k} |t_i - t_k|,  F_k = sum_all |t_i - t_k|
// Rank-tiles of 128, target-sorted + prefix sums -> O(1) range-|diff| queries:
//   A(t) = t*(2c-TS) - 2*St(c) + Stot,  c = #{t_i <= t}
// 2L_k - F_k = sum_{u<T} A_u - sum_{u>=T} A_u + 2*L_own(brute).
// K1: CUB radix 512x4 by pred desc (payload target) -> g_st; fused WARP-LOCAL per-tile
//     target bitonic sort + warp-scan prefix -> g_ts, g_pt (one warp == one tile).
// K2: one block per (row, tile); 2 threads per element split tiles 8/8 and brute in half.

constexpr int BB = 32;
constexpr int NN = 2048;
constexpr int TS = 128;
constexpr int NT = NN / TS;   // 16

__device__ float g_st[BB * NN];
__device__ float g_ts[BB * NN];
__device__ float g_pt[BB * NN];

__device__ __forceinline__ unsigned mono32(unsigned u) {
    return (u & 0x80000000u) ? ~u : (u | 0x80000000u);
}
__device__ __forceinline__ float unmono32(unsigned m) {
    unsigned o = (m & 0x80000000u) ? (m & 0x7fffffffu) : ~m;
    return __uint_as_float(o);
}
__device__ __forceinline__ unsigned cex32(unsigned v, unsigned o, int i, int j, int k) {
    bool up  = ((i & k) == 0);
    bool low = ((i & j) == 0);
    unsigned mn = (v < o) ? v : o;
    unsigned mx = (v < o) ? o : v;
    return (low == up) ? mn : mx;
}

// ---------- K1: radix sort by pred desc + warp-local tile prep ----------
using BRS = cub::BlockRadixSort<unsigned, 512, 4, unsigned>;

__global__ void __launch_bounds__(512) sort_kernel(const float* __restrict__ preds,
                                                   const float* __restrict__ targets,
                                                   float* __restrict__ out) {
    __shared__ typename BRS::TempStorage cubts;

    const int row = blockIdx.x;
    const int t   = threadIdx.x;
    if (row == 0 && t == 0) out[0] = 0.0f;   // stream-ordered before K2's atomics

    const float4 pv = ((const float4*)(preds + row * NN))[t];
    const float4 tv = ((const float4*)(targets + row * NN))[t];

    unsigned keys[4] = { mono32(__float_as_uint(pv.x)), mono32(__float_as_uint(pv.y)),
                         mono32(__float_as_uint(pv.z)), mono32(__float_as_uint(pv.w)) };
    unsigned vals[4] = { __float_as_uint(tv.x), __float_as_uint(tv.y),
                         __float_as_uint(tv.z), __float_as_uint(tv.w) };

    BRS(cubts).SortDescending(keys, vals);   // stable; thread t holds ranks 4t..4t+3

    ((float4*)(g_st + row * NN))[t] =
        make_float4(__uint_as_float(vals[0]), __uint_as_float(vals[1]),
                    __uint_as_float(vals[2]), __uint_as_float(vals[3]));

    // per-tile (== per-warp) ascending bitonic sort of 128 targets, 4 per lane
    const int lane = t & 31;
    const int i0 = 4 * lane;     // element index within tile for m[0]
    unsigned m[4] = { mono32(vals[0]), mono32(vals[1]), mono32(vals[2]), mono32(vals[3]) };

#pragma unroll
    for (int k = 2; k <= TS; k <<= 1) {
#pragma unroll
        for (int j = k >> 1; j > 0; j >>= 1) {
            if (j >= 4) {
                int dl = j >> 2;
#pragma unroll
                for (int q = 0; q < 4; q++) {
                    unsigned o = __shfl_xor_sync(0xffffffffu, m[q], dl);
                    m[q] = cex32(m[q], o, i0 + q, j, k);
                }
            } else if (j == 2) {
                bool up = ((i0 & k) == 0);     // same for all 4 local elements (k >= 4)
                unsigned n0 = min(m[0], m[2]), x0 = max(m[0], m[2]);
                unsigned n1 = min(m[1], m[3]), x1 = max(m[1], m[3]);
                m[0] = up ? n0 : x0; m[2] = up ? x0 : n0;
                m[1] = up ? n1 : x1; m[3] = up ? x1 : n1;
            } else { // j == 1
                bool up = ((i0 & k) == 0);
                unsigned n0 = min(m[0], m[1]), x0 = max(m[0], m[1]);
                unsigned n1 = min(m[2], m[3]), x1 = max(m[2], m[3]);
                m[0] = up ? n0 : x0; m[1] = up ? x0 : n0;
                m[2] = up ? n1 : x1; m[3] = up ? x1 : n1;
            }
        }
    }

    float s0 = unmono32(m[0]), s1 = unmono32(m[1]), s2 = unmono32(m[2]), s3 = unmono32(m[3]);

    // inclusive prefix within tile: warp scan of per-thread sums
    float mysum = (s0 + s1) + (s2 + s3);
    float sc = mysum;
#pragma unroll
    for (int off = 1; off < 32; off <<= 1) {
        float y = __shfl_up_sync(0xffffffffu, sc, off);
        if (lane >= off) sc += y;
    }
    float base = sc - mysum;
    float p0 = base + s0, p1 = p0 + s1, p2 = p1 + s2, p3 = p2 + s3;

    ((float4*)(g_ts + row * NN))[t] = make_float4(s0, s1, s2, s3);
    ((float4*)(g_pt + row * NN))[t] = make_float4(p0, p1, p2, p3);
}

// ---------- K2: per-element queries, 2 threads per element ----------
__global__ void __launch_bounds__(256) query_kernel(float* __restrict__ out) {
    __shared__ float ts_s[NN];
    __shared__ float pt_s[NN];
    __shared__ float st_s[TS];
    __shared__ float wsum[8];

    const int row = blockIdx.y;
    const int T   = blockIdx.x;      // chunk == own rank-tile (0..15)
    const int tid = threadIdx.x;

    for (int i = tid; i < NN; i += 256) {
        ts_s[i] = g_ts[row * NN + i];
        pt_s[i] = g_pt[row * NN + i];
    }
    if (tid < TS) st_s[tid] = g_st[row * NN + T * TS + tid];
    __syncthreads();

    const int e    = tid >> 1;       // element local rank 0..127
    const int half = tid & 1;
    const int a    = T * TS + e;
    const float ta = st_s[e];
    const float da = __log2f((float)(a + 3));

    // 8 interleaved binary searches over this half's tiles
    const int u0 = half * 8;
    int c[8];
#pragma unroll
    for (int q = 0; q < 8; q++) c[q] = 0;
#pragma unroll
    for (int s = TS / 2; s > 0; s >>= 1) {
#pragma unroll
        for (int q = 0; q < 8; q++) {
            if (ts_s[(u0 + q) * TS + c[q] + s - 1] <= ta) c[q] += s;
        }
    }

    float acc = 0.f;
#pragma unroll
    for (int q = 0; q < 8; q++) {
        int u = u0 + q;
        int cc = c[q];
        float St   = cc ? pt_s[u * TS + cc - 1] : 0.f;
        float Stot = pt_s[u * TS + TS - 1];
        float A = ta * (float)(2 * cc - TS) - 2.f * St + Stot;
        acc += (u < T) ? A : -A;
    }

    // own-tile earlier-rank brute, split between the pair
    const int lo = half ? (e >> 1) : 0;
    const int hi = half ? e : (e >> 1);
    float L = 0.f;
    for (int i = lo; i < hi; i++)
        L += fabsf(st_s[i] - ta);

    float res = da * (acc + 2.f * L);

#pragma unroll
    for (int off = 16; off > 0; off >>= 1)
        res += __shfl_down_sync(0xffffffffu, res, off);
    if ((tid & 31) == 0) wsum[tid >> 5] = res;
    __syncthreads();
    if (tid == 0) {
        float bs = 0.f;
#pragma unroll
        for (int w = 0; w < 8; w++) bs += wsum[w];
        atomicAdd(out, bs * (1.0f / (float)BB));
    }
}

extern "C" void kernel_launch(void* const* d_in, const int* in_sizes, int n_in,
                              void* d_out, int out_size) {
    const float* preds   = (const float*)d_in[0];
    const float* targets = (const float*)d_in[1];
    float* out = (float*)d_out;

    sort_kernel<<<BB, 512>>>(preds, targets, out);

    dim3 g2(NT, BB);
    query_kernel<<<g2, 256>>>(out);
}